// round 14
// baseline (speedup 1.0000x reference)
#include <cuda_runtime.h>
#include <cuda_bf16.h>
#include <cstdint>

#define LOG2E 1.4426950408889634f
#define NPTS 4096
#define NT 1024                       // 32x32 tiles of 128x128

// mma.sync m16n8k16 bf16 (row.col), f32 accum.
#define MMA16816(c, a, b0v, b1v)                                               \
    asm("mma.sync.aligned.m16n8k16.row.col.f32.bf16.bf16.f32 "                 \
        "{%0,%1,%2,%3}, {%4,%5,%6,%7}, {%8,%9}, {%0,%1,%2,%3};"                \
        : "+f"((c)[0]), "+f"((c)[1]), "+f"((c)[2]), "+f"((c)[3])               \
        : "r"((a)[0]), "r"((a)[1]), "r"((a)[2]), "r"((a)[3]),                  \
          "r"(b0v), "r"(b1v))

#define EX2(v) asm("ex2.approx.ftz.f32 %0, %0;" : "+f"(v))

// smem: double-buffered A/B (96B rows, K=48 dense), CS/DS, params
#define AOFF(b)  ((b) * 24576)
#define BOFF(b)  ((b) * 24576 + 12288)
#define CSOFF(b) (49152 + (b) * 1024)
#define DSOFF(b) (49152 + (b) * 1024 + 512)
#define PRMOFF   51200
#define SMEM_REQ 51328

extern __shared__ char smem[];

__device__ __forceinline__ uint32_t pack_bf2(__nv_bfloat16 a, __nv_bfloat16 b) {
    __nv_bfloat162 t(a, b);
    return *reinterpret_cast<uint32_t*>(&t);
}

// Persistent-CTA RBF: cov[i,j] = exp2( S_ij + c_i + d_j ),
// S = 3-term bf16 split GEMM (K=48: A=[uh|ul|uh], B=[vh|vh|vl]).
// Permuted B rows -> coalesced STG.128. k-groups software-pipelined:
// MMA(k) issued between EX2/STG of (k-1). Single-base-pointer addressing
// so all store/LDS offsets are SASS immediates.
__global__ void __launch_bounds__(256, 2) rbf_mma_p(
    const float* __restrict__ x,         // [4096,16]
    const float* __restrict__ xx,        // [4096,16]
    const float* __restrict__ scale_ff,  // [16]
    const float* __restrict__ var_ff,    // scalar
    float* __restrict__ out)             // [4096,4096]
{
    const int tid  = threadIdx.x;
    const int wid  = tid >> 5;
    const int lane = tid & 31;
    float* SINV = (float*)(smem + PRMOFF);   // [16] inv-scale, [16]=log2(var)

    if (tid >= 32 && tid < 48) {
        SINV[tid - 32] = 1.0f / log1pf(__expf(scale_ff[tid - 32]));
    } else if (tid == 48) {
        SINV[16] = log2f(log1pf(__expf(var_ff[0])));
    }

    const bool is_x = (tid < 128);
    const int rowid = tid & 127;

    int t = blockIdx.x;
    float4 ra, rb, rc, rd;
    if (t < NT) {
        const int bi0 = (t >> 5) * 128, bj0 = (t & 31) * 128;
        const float4* rowp = is_x
            ? (const float4*)(x  + (size_t)(bi0 + rowid) * 16)
            : (const float4*)(xx + (size_t)(bj0 + rowid) * 16);
        ra = rowp[0]; rb = rowp[1]; rc = rowp[2]; rd = rowp[3];
    }
    __syncthreads();   // SINV ready

    const int qrow = lane >> 2;
    const int qcol = lane & 3;
    const int wr = (wid & 3) * 32;
    const int wc = (wid >> 2) * 64;

    int buf = 0;
    while (t < NT) {
        const int bi0 = (t >> 5) * 128, bj0 = (t & 31) * 128;
        const int tn = t + gridDim.x;

        // ---- convert current rows -> smem[buf] ----
        {
            float vals[16] = {ra.x, ra.y, ra.z, ra.w, rb.x, rb.y, rb.z, rb.w,
                              rc.x, rc.y, rc.z, rc.w, rd.x, rd.y, rd.z, rd.w};
            uint32_t hp[8], lp[8];
            float s2 = 0.0f;
#pragma unroll
            for (int d = 0; d < 16; d += 2) {
                float u0 = vals[d] * SINV[d];
                float u1 = vals[d + 1] * SINV[d + 1];
                s2 = fmaf(u0, u0, fmaf(u1, u1, s2));
                float w0 = is_x ? u0 : (LOG2E * u0);
                float w1 = is_x ? u1 : (LOG2E * u1);
                __nv_bfloat16 h0 = __float2bfloat16_rn(w0);
                __nv_bfloat16 h1 = __float2bfloat16_rn(w1);
                __nv_bfloat16 l0 = __float2bfloat16_rn(w0 - __bfloat162float(h0));
                __nv_bfloat16 l1 = __float2bfloat16_rn(w1 - __bfloat162float(h1));
                hp[d >> 1] = pack_bf2(h0, h1);
                lp[d >> 1] = pack_bf2(l0, l1);
            }
            // pair-interleaved 8-word groups: phys = {w0,w4,w1,w5},{w2,w6,w3,w7}
            uint4 H0 = make_uint4(hp[0], hp[4], hp[1], hp[5]);
            uint4 H1 = make_uint4(hp[2], hp[6], hp[3], hp[7]);
            uint4 L0 = make_uint4(lp[0], lp[4], lp[1], lp[5]);
            uint4 L1 = make_uint4(lp[2], lp[6], lp[3], lp[7]);
            if (is_x) {
                uint4* dst = (uint4*)(smem + AOFF(buf) + rowid * 96);
                dst[0] = H0; dst[1] = H1;   // k0: uh
                dst[2] = L0; dst[3] = L1;   // k1: ul
                dst[4] = H0; dst[5] = H1;   // k2: uh
                ((float*)(smem + CSOFF(buf)))[rowid] = -0.5f * LOG2E * s2;
            } else {
                // permuted slot: j64 bits (k,qc,m,e) -> slot (k,m,qc,e)
                const int j64 = rowid & 63;
                const int slot = (j64 & 0x30) | ((j64 & 2) << 2) |
                                 ((j64 & 0xC) >> 1) | (j64 & 1);
                const int brow = (rowid & 64) + slot;
                uint4* dst = (uint4*)(smem + BOFF(buf) + brow * 96);
                dst[0] = H0; dst[1] = H1;   // k0: vh
                dst[2] = H0; dst[3] = H1;   // k1: vh
                dst[4] = L0; dst[5] = L1;   // k2: vl
                ((float*)(smem + DSOFF(buf)))[rowid] =
                    -0.5f * LOG2E * s2 + SINV[16];
            }
        }

        // ---- prefetch next tile's rows (in flight over MMA+epilogue) ----
        if (tn < NT) {
            const int nbi = (tn >> 5) * 128, nbj = (tn & 31) * 128;
            const float4* rowp = is_x
                ? (const float4*)(x  + (size_t)(nbi + rowid) * 16)
                : (const float4*)(xx + (size_t)(nbj + rowid) * 16);
            ra = rowp[0]; rb = rowp[1]; rc = rowp[2]; rd = rowp[3];
        }
        __syncthreads();   // smem[buf] ready

        // ---- base pointers (all further offsets are compile-time consts) ----
        const char*  Ab = smem + AOFF(buf) + (wr + qrow) * 96 + qcol * 8;
        const char*  Bb = smem + BOFF(buf) + (wc + qrow) * 96 + qcol * 8;
        const float* DJ = (const float*)(smem + DSOFF(buf)) + wc + 4 * qcol;
        const float* CSb = (const float*)(smem + CSOFF(buf)) + wr + qrow;
        float* ob = out + (size_t)(bi0 + wr + qrow) * NPTS + bj0 + wc + 4 * qcol;

        // hoist a-fragments: LDS.64 x12, immediate offsets
        uint32_t af[3][2][4];
#pragma unroll
        for (int ks = 0; ks < 3; ks++) {
#pragma unroll
            for (int mt = 0; mt < 2; mt++) {
                uint2 p = *(const uint2*)(Ab + mt * 1536 + ks * 32);
                uint2 q = *(const uint2*)(Ab + mt * 1536 + 768 + ks * 32);
                af[ks][mt][0] = p.x;
                af[ks][mt][1] = q.x;
                af[ks][mt][2] = p.y;
                af[ks][mt][3] = q.y;
            }
        }
        float ci[4];
        ci[0] = CSb[0];  ci[1] = CSb[8];  ci[2] = CSb[16]; ci[3] = CSb[24];

        // ---- software-pipelined k-groups: MMA(k) before EPI(k-1) ----
        float acc[2][2][2][4];   // [parity][nb][mt][4]

#define COMPUTE_GROUP(k)                                                       \
        {                                                                      \
            float4 dj = *(const float4*)(DJ + 16 * (k));                       \
            float (*ac)[2][4] = acc[(k) & 1];                                  \
            _Pragma("unroll")                                                  \
            for (int mt = 0; mt < 2; mt++) {                                   \
                ac[0][mt][0] = ci[2 * mt] + dj.x;                              \
                ac[0][mt][1] = ci[2 * mt] + dj.y;                              \
                ac[0][mt][2] = ci[2 * mt + 1] + dj.x;                          \
                ac[0][mt][3] = ci[2 * mt + 1] + dj.y;                          \
                ac[1][mt][0] = ci[2 * mt] + dj.z;                              \
                ac[1][mt][1] = ci[2 * mt] + dj.w;                              \
                ac[1][mt][2] = ci[2 * mt + 1] + dj.z;                          \
                ac[1][mt][3] = ci[2 * mt + 1] + dj.w;                          \
            }                                                                  \
            _Pragma("unroll")                                                  \
            for (int ks = 0; ks < 3; ks++) {                                   \
                uint2 b0 = *(const uint2*)(Bb + (k) * 1536 + ks * 32);         \
                uint2 b1 = *(const uint2*)(Bb + (k) * 1536 + 768 + ks * 32);   \
                MMA16816(ac[0][0], af[ks][0], b0.x, b0.y);                     \
                MMA16816(ac[0][1], af[ks][1], b0.x, b0.y);                     \
                MMA16816(ac[1][0], af[ks][0], b1.x, b1.y);                     \
                MMA16816(ac[1][1], af[ks][1], b1.x, b1.y);                     \
            }                                                                  \
        }

#define EPI_GROUP(k)                                                           \
        {                                                                      \
            float (*ac)[2][4] = acc[(k) & 1];                                  \
            _Pragma("unroll")                                                  \
            for (int mt = 0; mt < 2; mt++) {                                   \
                float f0 = ac[0][mt][0], f1 = ac[0][mt][1];                    \
                float f2 = ac[1][mt][0], f3 = ac[1][mt][1];                    \
                float g0 = ac[0][mt][2], g1 = ac[0][mt][3];                    \
                float g2 = ac[1][mt][2], g3 = ac[1][mt][3];                    \
                EX2(f0); EX2(f1); EX2(f2); EX2(f3);                            \
                EX2(g0); EX2(g1); EX2(g2); EX2(g3);                            \
                *(float4*)(ob + mt * (16 * NPTS) + 16 * (k)) =                 \
                    make_float4(f0, f1, f2, f3);                               \
                *(float4*)(ob + mt * (16 * NPTS) + 8 * NPTS + 16 * (k)) =      \
                    make_float4(g0, g1, g2, g3);                               \
            }                                                                  \
        }

        COMPUTE_GROUP(0)
        COMPUTE_GROUP(1)
        EPI_GROUP(0)
        COMPUTE_GROUP(2)
        EPI_GROUP(1)
        COMPUTE_GROUP(3)
        EPI_GROUP(2)
        EPI_GROUP(3)

#undef COMPUTE_GROUP
#undef EPI_GROUP

        t = tn;
        buf ^= 1;
    }
}

extern "C" void kernel_launch(void* const* d_in, const int* in_sizes, int n_in,
                              void* d_out, int out_size) {
    const float* x        = (const float*)d_in[0];
    const float* xx       = (const float*)d_in[1];
    const float* scale_ff = (const float*)d_in[2];
    const float* var_ff   = (const float*)d_in[3];
    float* out = (float*)d_out;

    int sms = 148;
    cudaDeviceGetAttribute(&sms, cudaDevAttrMultiProcessorCount, 0);
    int grid = 2 * sms;
    if (grid > NT) grid = NT;

    cudaFuncSetAttribute(rbf_mma_p, cudaFuncAttributeMaxDynamicSharedMemorySize,
                         SMEM_REQ);
    rbf_mma_p<<<grid, 256, SMEM_REQ>>>(x, xx, scale_ff, var_ff, out);
}